// round 16
// baseline (speedup 1.0000x reference)
#include <cuda_runtime.h>
#include <cstdint>

#define NBLK 592          // 4 blocks/SM * 148 SMs -> one wave
#define NTHR 256
#define STAGES 4
#define TILE_F4 256       // 256 float4 = 4KB per array per stage
#define SLOT_BYTES 4096

__device__ float        g_partials[NBLK];
__device__ unsigned int g_ticket;   // zero-init; reset by last block each launch

__device__ __forceinline__ unsigned smem_u32(const void* p) {
    return (unsigned)__cvta_generic_to_shared(p);
}

__device__ __forceinline__ void cp16(unsigned dst, const void* src) {
    asm volatile("cp.async.cg.shared.global [%0], [%1], 16;"
                 :: "r"(dst), "l"(src) : "memory");
}
#define CP_COMMIT() asm volatile("cp.async.commit_group;" ::: "memory")
#define CP_WAIT3()  asm volatile("cp.async.wait_group 3;" ::: "memory")

__global__ __launch_bounds__(NTHR, 4) void le_fused(
    const float* __restrict__ x,
    const float* __restrict__ decoded,
    const float* __restrict__ encoded,
    const float* __restrict__ latent,
    const float* __restrict__ rsrA,
    float* __restrict__ out,
    int B, int D, int E, int I)
{
    __shared__ float4 bx[STAGES][TILE_F4];     // 16KB (x ring)
    __shared__ float4 bd[STAGES][TILE_F4];     // 16KB (decoded ring)
    __shared__ float  sA[128 * 21];            // 10.5KB rsrA cache
    __shared__ float  red[NTHR];               // 1KB

    const int tid = threadIdx.x;
    const int bid = blockIdx.x;

    // rsrA cache (stride 21 -> conflict-free)
    for (int i = tid; i < E * I; i += NTHR) {
        int e = i / 20, k = i % 20;
        sA[e * 21 + k] = rsrA[i];
    }
    __syncthreads();

    const int n4 = (B * D) >> 2;          // float4 count per array
    const int nt = n4 / TILE_F4;          // 4KB tiles per array
    const float4* __restrict__ x4 = (const float4*)x;
    const float4* __restrict__ d4 = (const float4*)decoded;

    const int ntiles = (bid < nt) ? ((nt - bid + NBLK - 1) / NBLK) : 0;

    // per-thread private smem slots (this thread only ever touches these)
    const unsigned my_bx = smem_u32(&bx[0][tid]);
    const unsigned my_bd = smem_u32(&bd[0][tid]);

    // ---- Prologue: queue STAGES groups (empty-commit past the end) ----
    for (int lt = 0; lt < STAGES; lt++) {
        if (lt < ntiles) {
            const size_t g = (size_t)(bid + lt * NBLK) * TILE_F4 + tid;
            cp16(my_bx + lt * SLOT_BYTES, x4 + g);
            cp16(my_bd + lt * SLOT_BYTES, d4 + g);
        }
        CP_COMMIT();
    }

    // ======== Phase 2 (overlaps prologue stream): ========
    //          sum (encoded - latent@A^T)^2, 4 independent slots
    float acc2 = 0.0f;
    {
        const int gtid   = bid * NTHR + tid;
        const int stride = NBLK * NTHR;
        const int n2 = B * E;
        int j = gtid;
        const int s = stride;
        for (; j + 3 * s < n2; j += 4 * s) {
            float z0 = 0.f, z1 = 0.f, z2 = 0.f, z3 = 0.f;
            const int j0 = j, j1 = j + s, j2 = j + 2*s, j3 = j + 3*s;
            const float4* __restrict__ L0 = (const float4*)(latent + (j0 >> 7) * 20);
            const float4* __restrict__ L1 = (const float4*)(latent + (j1 >> 7) * 20);
            const float4* __restrict__ L2 = (const float4*)(latent + (j2 >> 7) * 20);
            const float4* __restrict__ L3 = (const float4*)(latent + (j3 >> 7) * 20);
            const float* __restrict__ A0 = sA + (j0 & 127) * 21;
            const float* __restrict__ A1 = sA + (j1 & 127) * 21;
            const float* __restrict__ A2 = sA + (j2 & 127) * 21;
            const float* __restrict__ A3 = sA + (j3 & 127) * 21;
            float e0 = encoded[j0], e1 = encoded[j1],
                  e2 = encoded[j2], e3 = encoded[j3];
            #pragma unroll
            for (int q = 0; q < 5; q++) {           // I == 20 = 5 float4
                float4 l0 = L0[q], l1 = L1[q], l2 = L2[q], l3 = L3[q];
                z0 = fmaf(l0.x, A0[4*q+0], z0); z0 = fmaf(l0.y, A0[4*q+1], z0);
                z0 = fmaf(l0.z, A0[4*q+2], z0); z0 = fmaf(l0.w, A0[4*q+3], z0);
                z1 = fmaf(l1.x, A1[4*q+0], z1); z1 = fmaf(l1.y, A1[4*q+1], z1);
                z1 = fmaf(l1.z, A1[4*q+2], z1); z1 = fmaf(l1.w, A1[4*q+3], z1);
                z2 = fmaf(l2.x, A2[4*q+0], z2); z2 = fmaf(l2.y, A2[4*q+1], z2);
                z2 = fmaf(l2.z, A2[4*q+2], z2); z2 = fmaf(l2.w, A2[4*q+3], z2);
                z3 = fmaf(l3.x, A3[4*q+0], z3); z3 = fmaf(l3.y, A3[4*q+1], z3);
                z3 = fmaf(l3.z, A3[4*q+2], z3); z3 = fmaf(l3.w, A3[4*q+3], z3);
            }
            float d;
            d = e0 - z0; acc2 = fmaf(d, d, acc2);
            d = e1 - z1; acc2 = fmaf(d, d, acc2);
            d = e2 - z2; acc2 = fmaf(d, d, acc2);
            d = e3 - z3; acc2 = fmaf(d, d, acc2);
        }
        for (; j < n2; j += s) {
            const float4* __restrict__ L = (const float4*)(latent + (j >> 7) * 20);
            const float* __restrict__ A = sA + (j & 127) * 21;
            float z = 0.f;
            #pragma unroll
            for (int q = 0; q < 5; q++) {
                float4 l = L[q];
                z = fmaf(l.x, A[4*q+0], z); z = fmaf(l.y, A[4*q+1], z);
                z = fmaf(l.z, A[4*q+2], z); z = fmaf(l.w, A[4*q+3], z);
            }
            float d = encoded[j] - z;
            acc2 = fmaf(d, d, acc2);
        }
    }

    // ======== Phase 1: per-thread cp.async pipeline, ZERO block sync ========
    // Each thread copies and consumes only its own slots; wait_group guards
    // its own groups; slot reuse is private. Commit every iter keeps count exact.
    float acc1 = 0.0f;
    for (int lt = 0; lt < ntiles; lt++) {
        const int slot = lt & (STAGES - 1);

        CP_WAIT3();   // retire group lt (4 outstanding -> 3)

        float4 a = *(const float4*)(bx[slot] + tid);
        float4 c = *(const float4*)(bd[slot] + tid);

        // consume before reissuing into the same slot
        float t;
        t = a.x - c.x; acc1 = fmaf(t, t, acc1);
        t = a.y - c.y; acc1 = fmaf(t, t, acc1);
        t = a.z - c.z; acc1 = fmaf(t, t, acc1);
        t = a.w - c.w; acc1 = fmaf(t, t, acc1);

        const int nxt = lt + STAGES;
        if (nxt < ntiles) {
            const size_t g = (size_t)(bid + nxt * NBLK) * TILE_F4 + tid;
            cp16(my_bx + slot * SLOT_BYTES, x4 + g);
            cp16(my_bd + slot * SLOT_BYTES, d4 + g);
        }
        CP_COMMIT();
    }
    // remainder (none for canonical shape, kept for safety)
    for (int i = nt * TILE_F4 + bid * NTHR + tid; i < n4; i += NBLK * NTHR) {
        float4 a = x4[i], c = d4[i];
        float t;
        t = a.x - c.x; acc1 = fmaf(t, t, acc1);
        t = a.y - c.y; acc1 = fmaf(t, t, acc1);
        t = a.z - c.z; acc1 = fmaf(t, t, acc1);
        t = a.w - c.w; acc1 = fmaf(t, t, acc1);
    }

    // ======== Gram term (block 0): w*Sg with w = 0.1*B/(I*I) ========
    float extra = 0.0f;
    if (bid == 0) {
        float sg = 0.0f;
        for (int t = tid; t < I * I; t += NTHR) {
            const int gi = t / 20, gj = t % 20;
            float acc = 0.0f;
            #pragma unroll 8
            for (int e = 0; e < 128; e++)
                acc = fmaf(sA[e * 21 + gi], sA[e * 21 + gj], acc);
            if (gi == gj) acc -= 1.0f;
            sg = fmaf(acc, acc, sg);
        }
        extra = (0.1f * (float)B / (float)(I * I)) * sg;
    }

    // ======== Deterministic block reduction ========
    red[tid] = acc1 + 1.1f * acc2 + extra;
    __syncthreads();
    for (int s = NTHR / 2; s > 0; s >>= 1) {
        if (tid < s) red[tid] += red[tid + s];
        __syncthreads();
    }

    // ======== Last-block final reduction ========
    __shared__ bool is_last;
    if (tid == 0) {
        g_partials[bid] = red[0];
        __threadfence();
        unsigned int t = atomicAdd(&g_ticket, 1u);
        is_last = (t == (unsigned int)(gridDim.x - 1));
    }
    __syncthreads();

    if (is_last) {
        __threadfence();
        float p = 0.0f;
        for (int k = tid; k < NBLK; k += NTHR)
            p += g_partials[k];
        red[tid] = p;
        __syncthreads();
        for (int s = NTHR / 2; s > 0; s >>= 1) {
            if (tid < s) red[tid] += red[tid + s];
            __syncthreads();
        }
        if (tid == 0) {
            out[0] = red[0] / (float)B;
            g_ticket = 0;
        }
    }
}

extern "C" void kernel_launch(void* const* d_in, const int* in_sizes, int n_in,
                              void* d_out, int out_size)
{
    const float* x       = (const float*)d_in[0];
    const float* encoded = (const float*)d_in[1];
    const float* latent  = (const float*)d_in[2];
    const float* decoded = (const float*)d_in[3];
    const float* rsrA    = (const float*)d_in[4];

    const int I = 20;                  // INTRINSIC
    const int B = in_sizes[2] / I;     // latent [B, I]
    const int E = in_sizes[1] / B;     // encoded [B, E]
    const int D = in_sizes[0] / B;     // x [B, D]

    le_fused<<<NBLK, NTHR>>>(x, decoded, encoded, latent, rsrA,
                             (float*)d_out, B, D, E, I);
}